// round 6
// baseline (speedup 1.0000x reference)
#include <cuda_runtime.h>
#include <cstdint>

#define HID   1024
#define NHEAD 16
#define HD    64
#define BATCH 2
#define SEQ   2048
#define BH    (BATCH*NHEAD)          // 32
#define MR    (BATCH*SEQ)            // 4096
#define QKVSZ (BH*SEQ*HD)            // 4194304 floats

// Scratch (device globals -- no allocation allowed)
__device__ float g_qkv[3*QKVSZ];     // Q|K|V [b,h,s,d], tf32-rounded
__device__ float g_ctx[MR*HID];      // attn out [b,s,h*d], tf32-rounded
__device__ float g_xa[MR*HID];       // x, tf32-rounded
__device__ float g_wqkv[3*HID*HID];  // qkv_w, tf32-rounded
__device__ float g_wout[HID*HID];    // out_w, tf32-rounded

__device__ __forceinline__ uint32_t f2tf32(float x) {
    uint32_t r; asm("cvt.rna.tf32.f32 %0, %1;" : "=r"(r) : "f"(x)); return r;
}
__device__ __forceinline__ void mma_tf32(
    float& d0, float& d1, float& d2, float& d3,
    uint32_t a0, uint32_t a1, uint32_t a2, uint32_t a3,
    uint32_t b0, uint32_t b1)
{
    asm volatile(
        "mma.sync.aligned.m16n8k8.row.col.f32.tf32.tf32.f32 "
        "{%0,%1,%2,%3}, {%4,%5,%6,%7}, {%8,%9}, {%0,%1,%2,%3};"
        : "+f"(d0), "+f"(d1), "+f"(d2), "+f"(d3)
        : "r"(a0), "r"(a1), "r"(a2), "r"(a3), "r"(b0), "r"(b1));
}

// ---------------------------------------------------------------------------
// Pre-pass: round x, qkv_w, out_w to tf32 (stored as float bits)
// ---------------------------------------------------------------------------
#define N4X  (MR*HID/4)
#define N4WQ (3*HID*HID/4)
#define N4WO (HID*HID/4)
__global__ __launch_bounds__(256)
void prep_kernel(const float* __restrict__ x, const float* __restrict__ wq,
                 const float* __restrict__ wo)
{
    int i = blockIdx.x * blockDim.x + threadIdx.x;
    const float4* src; uint4* dst; int j;
    if (i < N4X)            { src = (const float4*)x;  dst = (uint4*)g_xa;   j = i; }
    else if (i < N4X+N4WQ)  { src = (const float4*)wq; dst = (uint4*)g_wqkv; j = i - N4X; }
    else                    { src = (const float4*)wo; dst = (uint4*)g_wout; j = i - N4X - N4WQ; }
    float4 v = src[j];
    dst[j] = make_uint4(f2tf32(v.x), f2tf32(v.y), f2tf32(v.z), f2tf32(v.w));
}

// ---------------------------------------------------------------------------
// TF32 GEMM, BK=64 single-buffer synchronous staging (R4-proven pattern).
// C[M,N] = A[M,K]*W[N,K]^T + bias. BM=BN=128, 256 thr (8 warps 4x2), warp 32x64.
// MODE 0: A=g_xa, W=g_wqkv, scatter tf32-rounded into g_qkv [b,h,s,d]
// MODE 1: A=g_ctx, W=g_wout, plain write to C
// ---------------------------------------------------------------------------
#define GEMM_SMEM (2*128*68*4)
template<int MODE>
__global__ __launch_bounds__(256)
void gemm_tc(const float* __restrict__ bias, float* __restrict__ C,
             int Kd, int Nd)
{
    extern __shared__ uint32_t smem[];
    uint32_t* As = smem;              // [128][68]
    uint32_t* Bs = smem + 128*68;     // [128][68]

    const int tid = threadIdx.x;
    const int lane = tid & 31, wid = tid >> 5;
    const int g = lane >> 2, t4 = lane & 3;
    const int wm = wid & 3, wn = wid >> 2;
    const int m0 = blockIdx.y << 7, n0 = blockIdx.x << 7;
    const float* Ap = (MODE == 1) ? (const float*)g_ctx : (const float*)g_xa;
    const float* Wp = (MODE == 1) ? (const float*)g_wout : (const float*)g_wqkv;

    float acc[2][8][4];
#pragma unroll
    for (int mt = 0; mt < 2; mt++)
#pragma unroll
        for (int nt = 0; nt < 8; nt++)
#pragma unroll
            for (int r = 0; r < 4; r++) acc[mt][nt][r] = 0.f;

    for (int k0 = 0; k0 < Kd; k0 += 64) {
        __syncthreads();
#pragma unroll
        for (int it = 0; it < 8; it++) {
            int idx = tid + (it << 8);
            int row = idx >> 4, c = (idx & 15) << 2;
            *(uint4*)&As[row * 68 + c] =
                *(const uint4*)(Ap + (m0 + row) * Kd + k0 + c);
            *(uint4*)&Bs[row * 68 + c] =
                *(const uint4*)(Wp + (n0 + row) * Kd + k0 + c);
        }
        __syncthreads();
#pragma unroll
        for (int ks = 0; ks < 8; ks++) {
            const int kc = ks << 3;
            uint32_t af[2][4], bf[8][2];
#pragma unroll
            for (int mt = 0; mt < 2; mt++) {
                int r = wm * 32 + mt * 16;
                af[mt][0] = As[(r + g    ) * 68 + kc + t4];
                af[mt][1] = As[(r + g + 8) * 68 + kc + t4];
                af[mt][2] = As[(r + g    ) * 68 + kc + t4 + 4];
                af[mt][3] = As[(r + g + 8) * 68 + kc + t4 + 4];
            }
#pragma unroll
            for (int nt = 0; nt < 8; nt++) {
                int c = wn * 64 + nt * 8 + g;
                bf[nt][0] = Bs[c * 68 + kc + t4];
                bf[nt][1] = Bs[c * 68 + kc + t4 + 4];
            }
#pragma unroll
            for (int mt = 0; mt < 2; mt++)
#pragma unroll
                for (int nt = 0; nt < 8; nt++)
                    mma_tf32(acc[mt][nt][0], acc[mt][nt][1],
                             acc[mt][nt][2], acc[mt][nt][3],
                             af[mt][0], af[mt][1], af[mt][2], af[mt][3],
                             bf[nt][0], bf[nt][1]);
        }
    }

    // Epilogue
#pragma unroll
    for (int mt = 0; mt < 2; mt++) {
        int mA = m0 + wm * 32 + mt * 16 + g;
        int mB = mA + 8;
#pragma unroll
        for (int nt = 0; nt < 8; nt++) {
            int n = n0 + wn * 64 + nt * 8 + 2 * t4;
            float b0 = bias[n], b1 = bias[n + 1];
            float v00 = acc[mt][nt][0] + b0, v01 = acc[mt][nt][1] + b1;
            float v10 = acc[mt][nt][2] + b0, v11 = acc[mt][nt][3] + b1;
            if (MODE == 0) {
                int which = n >> 10;
                int wi = n & 1023;
                int h = wi >> 6, dd = wi & 63;
                {
                    int bb = mA >> 11, s = mA & 2047;
                    float* p = g_qkv + which * QKVSZ +
                               (((bb * NHEAD + h) * SEQ + s) << 6) + dd;
                    p[0] = __uint_as_float(f2tf32(v00));
                    p[1] = __uint_as_float(f2tf32(v01));
                }
                {
                    int bb = mB >> 11, s = mB & 2047;
                    float* p = g_qkv + which * QKVSZ +
                               (((bb * NHEAD + h) * SEQ + s) << 6) + dd;
                    p[0] = __uint_as_float(f2tf32(v10));
                    p[1] = __uint_as_float(f2tf32(v11));
                }
            } else {
                *(float2*)(C + mA * Nd + n) = make_float2(v00, v01);
                *(float2*)(C + mB * Nd + n) = make_float2(v10, v11);
            }
        }
    }
}

// ---------------------------------------------------------------------------
// TF32 flash attention, BKV=64, synchronous staging (R4-proven structure).
// CTA: 128 q-rows x 1 (b,h). 8 warps, 16 q-rows each.
// ---------------------------------------------------------------------------
#define ATTN_KS_OFF 0
#define ATTN_VS_OFF (64*68)
#define ATTN_PS_OFF (ATTN_VS_OFF + 64*72)
#define ATTN_MK_OFF (ATTN_PS_OFF + 8*16*68)
#define ATTN_SMEM   ((ATTN_MK_OFF + SEQ) * 4)
__global__ __launch_bounds__(256)
void attn_tc(const int* __restrict__ mask)
{
    extern __shared__ uint32_t smem[];
    uint32_t* Ks = smem + ATTN_KS_OFF;   // [64][68]
    uint32_t* Vs = smem + ATTN_VS_OFF;   // [64][72]
    uint32_t* Ps = smem + ATTN_PS_OFF;   // [8][16*68]
    int*      msk = (int*)(smem + ATTN_MK_OFF);

    const int tid = threadIdx.x;
    const int lane = tid & 31, wid = tid >> 5;
    const int g = lane >> 2, t4 = lane & 3;
    const int bh = blockIdx.y;
    const int bb = bh >> 4, h = bh & 15;
    const int q0 = blockIdx.x << 7, qr = q0 + wid * 16;

    const float* Qg = g_qkv + bh * (SEQ * HD);
    const float* Kg = Qg + QKVSZ;
    const float* Vg = Qg + 2 * QKVSZ;
    uint32_t* Pw = Ps + wid * (16 * 68);

    // mask row -> smem (first read is after the first staging barrier)
#pragma unroll
    for (int it = 0; it < SEQ / 256; it++)
        msk[tid + it * 256] = mask[bb * SEQ + tid + it * 256];

    // Q fragments (16x64), already tf32-rounded in gmem
    uint32_t qf[8][4];
#pragma unroll
    for (int kt = 0; kt < 8; kt++) {
        const float* qp = Qg + (qr + g) * HD + kt * 8 + t4;
        qf[kt][0] = __float_as_uint(qp[0]);
        qf[kt][1] = __float_as_uint(qp[8 * HD]);
        qf[kt][2] = __float_as_uint(qp[4]);
        qf[kt][3] = __float_as_uint(qp[8 * HD + 4]);
    }

    float of[8][4];
#pragma unroll
    for (int nt = 0; nt < 8; nt++)
#pragma unroll
        for (int r = 0; r < 4; r++) of[nt][r] = 0.f;
    float m0r = -1e30f, m1r = -1e30f, l0r = 0.f, l1r = 0.f;

    for (int it = 0; it < SEQ / 64; it++) {
        const int kvb = it * 64;
        __syncthreads();   // prior-iteration reads of Ks/Vs complete
#pragma unroll
        for (int it2 = 0; it2 < 4; it2++) {
            int idx = tid + (it2 << 8);
            int row = idx >> 4, c = (idx & 15) << 2;
            *(uint4*)&Ks[row * 68 + c] =
                *(const uint4*)(Kg + (kvb + row) * HD + c);
            *(uint4*)&Vs[row * 72 + c] =
                *(const uint4*)(Vg + (kvb + row) * HD + c);
        }
        __syncthreads();

        // S = Q*K^T (16x64 per warp)
        float sf[8][4];
#pragma unroll
        for (int nt = 0; nt < 8; nt++)
#pragma unroll
            for (int r = 0; r < 4; r++) sf[nt][r] = 0.f;
#pragma unroll
        for (int nt = 0; nt < 8; nt++)
#pragma unroll
            for (int kt = 0; kt < 8; kt++) {
                uint32_t b0 = Ks[(nt * 8 + g) * 68 + kt * 8 + t4];
                uint32_t b1 = Ks[(nt * 8 + g) * 68 + kt * 8 + t4 + 4];
                mma_tf32(sf[nt][0], sf[nt][1], sf[nt][2], sf[nt][3],
                         qf[kt][0], qf[kt][1], qf[kt][2], qf[kt][3], b0, b1);
            }

        // mask + scale + online softmax (rows g, g+8)
        float lm0 = -1e30f, lm1 = -1e30f;
#pragma unroll
        for (int nt = 0; nt < 8; nt++) {
            int c = kvb + nt * 8 + 2 * t4;
            int k0m = msk[c], k1m = msk[c + 1];
            sf[nt][0] = k0m ? sf[nt][0] * 0.125f : -1e9f;
            sf[nt][1] = k1m ? sf[nt][1] * 0.125f : -1e9f;
            sf[nt][2] = k0m ? sf[nt][2] * 0.125f : -1e9f;
            sf[nt][3] = k1m ? sf[nt][3] * 0.125f : -1e9f;
            lm0 = fmaxf(lm0, fmaxf(sf[nt][0], sf[nt][1]));
            lm1 = fmaxf(lm1, fmaxf(sf[nt][2], sf[nt][3]));
        }
        lm0 = fmaxf(lm0, __shfl_xor_sync(0xffffffffu, lm0, 1));
        lm0 = fmaxf(lm0, __shfl_xor_sync(0xffffffffu, lm0, 2));
        lm1 = fmaxf(lm1, __shfl_xor_sync(0xffffffffu, lm1, 1));
        lm1 = fmaxf(lm1, __shfl_xor_sync(0xffffffffu, lm1, 2));
        float nm0 = fmaxf(m0r, lm0), nm1 = fmaxf(m1r, lm1);
        float cr0 = __expf(m0r - nm0), cr1 = __expf(m1r - nm1);
        m0r = nm0; m1r = nm1;

        __syncwarp();   // prior PV reads of Pw retire before overwrite
        float ls0 = 0.f, ls1 = 0.f;
#pragma unroll
        for (int nt = 0; nt < 8; nt++) {
            float p00 = __expf(sf[nt][0] - nm0);
            float p01 = __expf(sf[nt][1] - nm0);
            float p10 = __expf(sf[nt][2] - nm1);
            float p11 = __expf(sf[nt][3] - nm1);
            ls0 += p00 + p01; ls1 += p10 + p11;
            int c = nt * 8 + 2 * t4;
            Pw[g * 68 + c]           = f2tf32(p00);
            Pw[g * 68 + c + 1]       = f2tf32(p01);
            Pw[(g + 8) * 68 + c]     = f2tf32(p10);
            Pw[(g + 8) * 68 + c + 1] = f2tf32(p11);
        }
        ls0 += __shfl_xor_sync(0xffffffffu, ls0, 1);
        ls0 += __shfl_xor_sync(0xffffffffu, ls0, 2);
        ls1 += __shfl_xor_sync(0xffffffffu, ls1, 1);
        ls1 += __shfl_xor_sync(0xffffffffu, ls1, 2);
        l0r = l0r * cr0 + ls0;
        l1r = l1r * cr1 + ls1;
#pragma unroll
        for (int nt = 0; nt < 8; nt++) {
            of[nt][0] *= cr0; of[nt][1] *= cr0;
            of[nt][2] *= cr1; of[nt][3] *= cr1;
        }
        __syncwarp();

        // O += P*V  (P 16x64, V 64x64)
#pragma unroll
        for (int kt = 0; kt < 8; kt++) {
            uint32_t pa0 = Pw[g * 68 + kt * 8 + t4];
            uint32_t pa1 = Pw[(g + 8) * 68 + kt * 8 + t4];
            uint32_t pa2 = Pw[g * 68 + kt * 8 + t4 + 4];
            uint32_t pa3 = Pw[(g + 8) * 68 + kt * 8 + t4 + 4];
#pragma unroll
            for (int nt = 0; nt < 8; nt++) {
                uint32_t b0 = Vs[(kt * 8 + t4) * 72 + nt * 8 + g];
                uint32_t b1 = Vs[(kt * 8 + t4 + 4) * 72 + nt * 8 + g];
                mma_tf32(of[nt][0], of[nt][1], of[nt][2], of[nt][3],
                         pa0, pa1, pa2, pa3, b0, b1);
            }
        }
    }

    // Epilogue: normalize, round to tf32, store [b,s,h*d]
    float inv0 = 1.0f / l0r, inv1 = 1.0f / l1r;
#pragma unroll
    for (int nt = 0; nt < 8; nt++) {
        int c = h * HD + nt * 8 + 2 * t4;
        float* p0 = g_ctx + (bb * SEQ + qr + g) * HID + c;
        float* p1 = g_ctx + (bb * SEQ + qr + g + 8) * HID + c;
        *(float2*)p0 = make_float2(__uint_as_float(f2tf32(of[nt][0] * inv0)),
                                   __uint_as_float(f2tf32(of[nt][1] * inv0)));
        *(float2*)p1 = make_float2(__uint_as_float(f2tf32(of[nt][2] * inv1)),
                                   __uint_as_float(f2tf32(of[nt][3] * inv1)));
    }
}

// ---------------------------------------------------------------------------
extern "C" void kernel_launch(void* const* d_in, const int* in_sizes, int n_in,
                              void* d_out, int out_size)
{
    (void)in_sizes; (void)n_in; (void)out_size;
    const float* x     = (const float*)d_in[0];
    const int*   mask  = (const int*)  d_in[1];
    const float* qkv_w = (const float*)d_in[2];
    const float* qkv_b = (const float*)d_in[3];
    const float* out_w = (const float*)d_in[4];
    const float* out_b = (const float*)d_in[5];

    cudaFuncSetAttribute(gemm_tc<0>, cudaFuncAttributeMaxDynamicSharedMemorySize, GEMM_SMEM);
    cudaFuncSetAttribute(gemm_tc<1>, cudaFuncAttributeMaxDynamicSharedMemorySize, GEMM_SMEM);
    cudaFuncSetAttribute(attn_tc,    cudaFuncAttributeMaxDynamicSharedMemorySize, ATTN_SMEM);

    prep_kernel<<<(N4X + N4WQ + N4WO) / 256, 256>>>(x, qkv_w, out_w);
    gemm_tc<0><<<dim3(3 * HID / 128, MR / 128), 256, GEMM_SMEM>>>(qkv_b, nullptr, HID, 3 * HID);
    attn_tc<<<dim3(SEQ / 128, BH), 256, ATTN_SMEM>>>(mask);
    gemm_tc<1><<<dim3(HID / 128, MR / 128), 256, GEMM_SMEM>>>(out_b, (float*)d_out, HID, HID);
}

// round 8
// speedup vs baseline: 1.0513x; 1.0513x over previous
#include <cuda_runtime.h>
#include <cstdint>

#define HID   1024
#define NHEAD 16
#define HD    64
#define BATCH 2
#define SEQ   2048
#define BH    (BATCH*NHEAD)          // 32
#define MR    (BATCH*SEQ)            // 4096
#define QKVSZ (BH*SEQ*HD)            // 4194304 floats

// Scratch (device globals -- no allocation allowed)
__device__ float g_qkv[3*QKVSZ];     // Q|K|V [b,h,s,d], tf32-rounded
__device__ float g_ctx[MR*HID];      // attn out [b,s,h*d], tf32-rounded
__device__ float g_xa[MR*HID];       // x, tf32-rounded
__device__ float g_wqkv[3*HID*HID];  // qkv_w, tf32-rounded
__device__ float g_wout[HID*HID];    // out_w, tf32-rounded

__device__ __forceinline__ uint32_t f2tf32(float x) {
    uint32_t r; asm("cvt.rna.tf32.f32 %0, %1;" : "=r"(r) : "f"(x)); return r;
}
__device__ __forceinline__ void mma_tf32(
    float& d0, float& d1, float& d2, float& d3,
    uint32_t a0, uint32_t a1, uint32_t a2, uint32_t a3,
    uint32_t b0, uint32_t b1)
{
    asm volatile(
        "mma.sync.aligned.m16n8k8.row.col.f32.tf32.tf32.f32 "
        "{%0,%1,%2,%3}, {%4,%5,%6,%7}, {%8,%9}, {%0,%1,%2,%3};"
        : "+f"(d0), "+f"(d1), "+f"(d2), "+f"(d3)
        : "r"(a0), "r"(a1), "r"(a2), "r"(a3), "r"(b0), "r"(b1));
}

// ---------------------------------------------------------------------------
// Pre-pass: round x, qkv_w, out_w to tf32 (stored as float bits)
// ---------------------------------------------------------------------------
#define N4X  (MR*HID/4)
#define N4WQ (3*HID*HID/4)
#define N4WO (HID*HID/4)
__global__ __launch_bounds__(256)
void prep_kernel(const float* __restrict__ x, const float* __restrict__ wq,
                 const float* __restrict__ wo)
{
    int i = blockIdx.x * blockDim.x + threadIdx.x;
    const float4* src; uint4* dst; int j;
    if (i < N4X)            { src = (const float4*)x;  dst = (uint4*)g_xa;   j = i; }
    else if (i < N4X+N4WQ)  { src = (const float4*)wq; dst = (uint4*)g_wqkv; j = i - N4X; }
    else                    { src = (const float4*)wo; dst = (uint4*)g_wout; j = i - N4X - N4WQ; }
    float4 v = src[j];
    dst[j] = make_uint4(f2tf32(v.x), f2tf32(v.y), f2tf32(v.z), f2tf32(v.w));
}

// ---------------------------------------------------------------------------
// TF32 GEMM, BK=32, double-buffered smem + register-prefetch pipeline.
// One __syncthreads per K-iteration; LDG of next tile overlaps MMA compute.
// Dynamic smem 73728 B (< proven-launchable 78848 B).
// ---------------------------------------------------------------------------
#define GEMM_SMEM (2*2*128*36*4)
template<int MODE>
__global__ __launch_bounds__(256, 1)
void gemm_tc(const float* __restrict__ bias, float* __restrict__ C,
             int Kd, int Nd)
{
    extern __shared__ uint32_t smem[];
    uint32_t* As = smem;                 // [2][128][36]
    uint32_t* Bs = smem + 2*128*36;      // [2][128][36]

    const int tid = threadIdx.x;
    const int lane = tid & 31, wid = tid >> 5;
    const int g = lane >> 2, t4 = lane & 3;
    const int wm = wid & 3, wn = wid >> 2;
    const int m0 = blockIdx.y << 7, n0 = blockIdx.x << 7;
    const float* Ap = (MODE == 1) ? (const float*)g_ctx : (const float*)g_xa;
    const float* Wp = (MODE == 1) ? (const float*)g_wout : (const float*)g_wqkv;

    const int lrow = tid >> 3, lc = (tid & 7) << 2;

    float acc[2][8][4];
#pragma unroll
    for (int mt = 0; mt < 2; mt++)
#pragma unroll
        for (int nt = 0; nt < 8; nt++)
#pragma unroll
            for (int r = 0; r < 4; r++) acc[mt][nt][r] = 0.f;

    uint4 ra[4], rb[4];
#define G_LDG(k0)                                                             \
    {                                                                         \
        _Pragma("unroll")                                                     \
        for (int it = 0; it < 4; it++) {                                      \
            int row = lrow + it * 32;                                         \
            ra[it] = *(const uint4*)(Ap + (m0 + row) * Kd + (k0) + lc);       \
            rb[it] = *(const uint4*)(Wp + (n0 + row) * Kd + (k0) + lc);       \
        }                                                                     \
    }
#define G_STS(st)                                                             \
    {                                                                         \
        _Pragma("unroll")                                                     \
        for (int it = 0; it < 4; it++) {                                      \
            int row = lrow + it * 32;                                         \
            *(uint4*)&As[((st) * 128 + row) * 36 + lc] = ra[it];              \
            *(uint4*)&Bs[((st) * 128 + row) * 36 + lc] = rb[it];              \
        }                                                                     \
    }

    G_LDG(0);
    G_STS(0);
    __syncthreads();

    const int KIT = Kd >> 5;
    for (int ki = 0; ki < KIT; ki++) {
        const int cur = ki & 1;
        if (ki + 1 < KIT) G_LDG((ki + 1) << 5);   // overlaps MMAs below
        const uint32_t* Ac = As + cur * (128 * 36);
        const uint32_t* Bc = Bs + cur * (128 * 36);
#pragma unroll
        for (int ks = 0; ks < 4; ks++) {
            const int kc = ks << 3;
            uint32_t af[2][4], bf[8][2];
#pragma unroll
            for (int mt = 0; mt < 2; mt++) {
                int r = wm * 32 + mt * 16;
                af[mt][0] = Ac[(r + g    ) * 36 + kc + t4];
                af[mt][1] = Ac[(r + g + 8) * 36 + kc + t4];
                af[mt][2] = Ac[(r + g    ) * 36 + kc + t4 + 4];
                af[mt][3] = Ac[(r + g + 8) * 36 + kc + t4 + 4];
            }
#pragma unroll
            for (int nt = 0; nt < 8; nt++) {
                int c = wn * 64 + nt * 8 + g;
                bf[nt][0] = Bc[c * 36 + kc + t4];
                bf[nt][1] = Bc[c * 36 + kc + t4 + 4];
            }
#pragma unroll
            for (int mt = 0; mt < 2; mt++)
#pragma unroll
                for (int nt = 0; nt < 8; nt++)
                    mma_tf32(acc[mt][nt][0], acc[mt][nt][1],
                             acc[mt][nt][2], acc[mt][nt][3],
                             af[mt][0], af[mt][1], af[mt][2], af[mt][3],
                             bf[nt][0], bf[nt][1]);
        }
        if (ki + 1 < KIT) {
            G_STS(cur ^ 1);
            __syncthreads();
        }
    }
#undef G_LDG
#undef G_STS

    // Epilogue
#pragma unroll
    for (int mt = 0; mt < 2; mt++) {
        int mA = m0 + wm * 32 + mt * 16 + g;
        int mB = mA + 8;
#pragma unroll
        for (int nt = 0; nt < 8; nt++) {
            int n = n0 + wn * 64 + nt * 8 + 2 * t4;
            float b0 = bias[n], b1 = bias[n + 1];
            float v00 = acc[mt][nt][0] + b0, v01 = acc[mt][nt][1] + b1;
            float v10 = acc[mt][nt][2] + b0, v11 = acc[mt][nt][3] + b1;
            if (MODE == 0) {
                int which = n >> 10;
                int wi = n & 1023;
                int h = wi >> 6, dd = wi & 63;
                {
                    int bb = mA >> 11, s = mA & 2047;
                    float* p = g_qkv + which * QKVSZ +
                               (((bb * NHEAD + h) * SEQ + s) << 6) + dd;
                    p[0] = __uint_as_float(f2tf32(v00));
                    p[1] = __uint_as_float(f2tf32(v01));
                }
                {
                    int bb = mB >> 11, s = mB & 2047;
                    float* p = g_qkv + which * QKVSZ +
                               (((bb * NHEAD + h) * SEQ + s) << 6) + dd;
                    p[0] = __uint_as_float(f2tf32(v10));
                    p[1] = __uint_as_float(f2tf32(v11));
                }
            } else {
                *(float2*)(C + mA * Nd + n) = make_float2(v00, v01);
                *(float2*)(C + mB * Nd + n) = make_float2(v10, v11);
            }
        }
    }
}

// ---------------------------------------------------------------------------
// TF32 flash attention, BKV=64, synchronous staging (R6-proven structure),
// softmax scale folded into Q fragments (exact, *2^-3).
// Dynamic smem 78848 B (proven launchable in R6).
// ---------------------------------------------------------------------------
#define ATTN_KS_OFF 0
#define ATTN_VS_OFF (64*68)
#define ATTN_PS_OFF (ATTN_VS_OFF + 64*72)
#define ATTN_MK_OFF (ATTN_PS_OFF + 8*16*68)
#define ATTN_SMEM   ((ATTN_MK_OFF + SEQ) * 4)
__global__ __launch_bounds__(256)
void attn_tc(const int* __restrict__ mask)
{
    extern __shared__ uint32_t smem[];
    uint32_t* Ks = smem + ATTN_KS_OFF;   // [64][68]
    uint32_t* Vs = smem + ATTN_VS_OFF;   // [64][72]
    uint32_t* Ps = smem + ATTN_PS_OFF;   // [8][16*68]
    int*      msk = (int*)(smem + ATTN_MK_OFF);

    const int tid = threadIdx.x;
    const int lane = tid & 31, wid = tid >> 5;
    const int g = lane >> 2, t4 = lane & 3;
    const int bh = blockIdx.y;
    const int bb = bh >> 4, h = bh & 15;
    const int q0 = blockIdx.x << 7, qr = q0 + wid * 16;

    const float* Qg = g_qkv + bh * (SEQ * HD);
    const float* Kg = Qg + QKVSZ;
    const float* Vg = Qg + 2 * QKVSZ;
    uint32_t* Pw = Ps + wid * (16 * 68);

    // mask row -> smem (first read is after the first staging barrier)
#pragma unroll
    for (int it = 0; it < SEQ / 256; it++)
        msk[tid + it * 256] = mask[bb * SEQ + tid + it * 256];

    // Q fragments (16x64) with softmax scale folded in (exact: *2^-3)
    uint32_t qf[8][4];
#pragma unroll
    for (int kt = 0; kt < 8; kt++) {
        const float* qp = Qg + (qr + g) * HD + kt * 8 + t4;
        qf[kt][0] = __float_as_uint(qp[0]          * 0.125f);
        qf[kt][1] = __float_as_uint(qp[8 * HD]     * 0.125f);
        qf[kt][2] = __float_as_uint(qp[4]          * 0.125f);
        qf[kt][3] = __float_as_uint(qp[8 * HD + 4] * 0.125f);
    }

    float of[8][4];
#pragma unroll
    for (int nt = 0; nt < 8; nt++)
#pragma unroll
        for (int r = 0; r < 4; r++) of[nt][r] = 0.f;
    float m0r = -1e30f, m1r = -1e30f, l0r = 0.f, l1r = 0.f;

    for (int it = 0; it < SEQ / 64; it++) {
        const int kvb = it * 64;
        __syncthreads();   // prior-iteration reads of Ks/Vs complete
#pragma unroll
        for (int it2 = 0; it2 < 4; it2++) {
            int idx = tid + (it2 << 8);
            int row = idx >> 4, c = (idx & 15) << 2;
            *(uint4*)&Ks[row * 68 + c] =
                *(const uint4*)(Kg + (kvb + row) * HD + c);
            *(uint4*)&Vs[row * 72 + c] =
                *(const uint4*)(Vg + (kvb + row) * HD + c);
        }
        __syncthreads();

        // S = (Q*scale) * K^T (16x64 per warp)
        float sf[8][4];
#pragma unroll
        for (int nt = 0; nt < 8; nt++)
#pragma unroll
            for (int r = 0; r < 4; r++) sf[nt][r] = 0.f;
#pragma unroll
        for (int nt = 0; nt < 8; nt++)
#pragma unroll
            for (int kt = 0; kt < 8; kt++) {
                uint32_t b0 = Ks[(nt * 8 + g) * 68 + kt * 8 + t4];
                uint32_t b1 = Ks[(nt * 8 + g) * 68 + kt * 8 + t4 + 4];
                mma_tf32(sf[nt][0], sf[nt][1], sf[nt][2], sf[nt][3],
                         qf[kt][0], qf[kt][1], qf[kt][2], qf[kt][3], b0, b1);
            }

        // mask + online softmax (rows g, g+8)
        float lm0 = -1e30f, lm1 = -1e30f;
#pragma unroll
        for (int nt = 0; nt < 8; nt++) {
            int c = kvb + nt * 8 + 2 * t4;
            int k0m = msk[c], k1m = msk[c + 1];
            sf[nt][0] = k0m ? sf[nt][0] : -1e9f;
            sf[nt][1] = k1m ? sf[nt][1] : -1e9f;
            sf[nt][2] = k0m ? sf[nt][2] : -1e9f;
            sf[nt][3] = k1m ? sf[nt][3] : -1e9f;
            lm0 = fmaxf(lm0, fmaxf(sf[nt][0], sf[nt][1]));
            lm1 = fmaxf(lm1, fmaxf(sf[nt][2], sf[nt][3]));
        }
        lm0 = fmaxf(lm0, __shfl_xor_sync(0xffffffffu, lm0, 1));
        lm0 = fmaxf(lm0, __shfl_xor_sync(0xffffffffu, lm0, 2));
        lm1 = fmaxf(lm1, __shfl_xor_sync(0xffffffffu, lm1, 1));
        lm1 = fmaxf(lm1, __shfl_xor_sync(0xffffffffu, lm1, 2));
        float nm0 = fmaxf(m0r, lm0), nm1 = fmaxf(m1r, lm1);
        float cr0 = __expf(m0r - nm0), cr1 = __expf(m1r - nm1);
        m0r = nm0; m1r = nm1;

        __syncwarp();   // prior PV reads of Pw retire before overwrite
        float ls0 = 0.f, ls1 = 0.f;
#pragma unroll
        for (int nt = 0; nt < 8; nt++) {
            float p00 = __expf(sf[nt][0] - nm0);
            float p01 = __expf(sf[nt][1] - nm0);
            float p10 = __expf(sf[nt][2] - nm1);
            float p11 = __expf(sf[nt][3] - nm1);
            ls0 += p00 + p01; ls1 += p10 + p11;
            int c = nt * 8 + 2 * t4;
            Pw[g * 68 + c]           = f2tf32(p00);
            Pw[g * 68 + c + 1]       = f2tf32(p01);
            Pw[(g + 8) * 68 + c]     = f2tf32(p10);
            Pw[(g + 8) * 68 + c + 1] = f2tf32(p11);
        }
        ls0 += __shfl_xor_sync(0xffffffffu, ls0, 1);
        ls0 += __shfl_xor_sync(0xffffffffu, ls0, 2);
        ls1 += __shfl_xor_sync(0xffffffffu, ls1, 1);
        ls1 += __shfl_xor_sync(0xffffffffu, ls1, 2);
        l0r = l0r * cr0 + ls0;
        l1r = l1r * cr1 + ls1;
#pragma unroll
        for (int nt = 0; nt < 8; nt++) {
            of[nt][0] *= cr0; of[nt][1] *= cr0;
            of[nt][2] *= cr1; of[nt][3] *= cr1;
        }
        __syncwarp();

        // O += P*V  (P 16x64, V 64x64)
#pragma unroll
        for (int kt = 0; kt < 8; kt++) {
            uint32_t pa0 = Pw[g * 68 + kt * 8 + t4];
            uint32_t pa1 = Pw[(g + 8) * 68 + kt * 8 + t4];
            uint32_t pa2 = Pw[g * 68 + kt * 8 + t4 + 4];
            uint32_t pa3 = Pw[(g + 8) * 68 + kt * 8 + t4 + 4];
#pragma unroll
            for (int nt = 0; nt < 8; nt++) {
                uint32_t b0 = Vs[(kt * 8 + t4) * 72 + nt * 8 + g];
                uint32_t b1 = Vs[(kt * 8 + t4 + 4) * 72 + nt * 8 + g];
                mma_tf32(of[nt][0], of[nt][1], of[nt][2], of[nt][3],
                         pa0, pa1, pa2, pa3, b0, b1);
            }
        }
    }

    // Epilogue: normalize, round to tf32, store [b,s,h*d]
    float inv0 = 1.0f / l0r, inv1 = 1.0f / l1r;
#pragma unroll
    for (int nt = 0; nt < 8; nt++) {
        int c = h * HD + nt * 8 + 2 * t4;
        float* p0 = g_ctx + (bb * SEQ + qr + g) * HID + c;
        float* p1 = g_ctx + (bb * SEQ + qr + g + 8) * HID + c;
        *(float2*)p0 = make_float2(__uint_as_float(f2tf32(of[nt][0] * inv0)),
                                   __uint_as_float(f2tf32(of[nt][1] * inv0)));
        *(float2*)p1 = make_float2(__uint_as_float(f2tf32(of[nt][2] * inv1)),
                                   __uint_as_float(f2tf32(of[nt][3] * inv1)));
    }
}

// ---------------------------------------------------------------------------
extern "C" void kernel_launch(void* const* d_in, const int* in_sizes, int n_in,
                              void* d_out, int out_size)
{
    (void)in_sizes; (void)n_in; (void)out_size;
    const float* x     = (const float*)d_in[0];
    const int*   mask  = (const int*)  d_in[1];
    const float* qkv_w = (const float*)d_in[2];
    const float* qkv_b = (const float*)d_in[3];
    const float* out_w = (const float*)d_in[4];
    const float* out_b = (const float*)d_in[5];

    cudaFuncSetAttribute(gemm_tc<0>, cudaFuncAttributeMaxDynamicSharedMemorySize, GEMM_SMEM);
    cudaFuncSetAttribute(gemm_tc<1>, cudaFuncAttributeMaxDynamicSharedMemorySize, GEMM_SMEM);
    cudaFuncSetAttribute(attn_tc,    cudaFuncAttributeMaxDynamicSharedMemorySize, ATTN_SMEM);

    prep_kernel<<<(N4X + N4WQ + N4WO) / 256, 256>>>(x, qkv_w, out_w);
    gemm_tc<0><<<dim3(3 * HID / 128, MR / 128), 256, GEMM_SMEM>>>(qkv_b, nullptr, HID, 3 * HID);
    attn_tc<<<dim3(SEQ / 128, BH), 256, ATTN_SMEM>>>(mask);
    gemm_tc<1><<<dim3(HID / 128, MR / 128), 256, GEMM_SMEM>>>(out_b, (float*)d_out, HID, HID);
}

// round 12
// speedup vs baseline: 1.1575x; 1.1010x over previous
#include <cuda_runtime.h>
#include <cstdint>

#define HID   1024
#define NHEAD 16
#define HD    64
#define BATCH 2
#define SEQ   2048
#define BH    (BATCH*NHEAD)          // 32
#define MR    (BATCH*SEQ)            // 4096
#define QKVSZ (BH*SEQ*HD)            // 4194304 floats

// Scratch (device globals -- no allocation allowed)
__device__ float g_qkv[3*QKVSZ];     // Q|K|V [b,h,s,d], tf32-rounded
__device__ float g_ctx[MR*HID];      // attn out [b,s,h*d], tf32-rounded
__device__ float g_xa[MR*HID];       // x, tf32-rounded
__device__ float g_wqkv[3*HID*HID];  // qkv_w, tf32-rounded
__device__ float g_wout[HID*HID];    // out_w, tf32-rounded

__device__ __forceinline__ uint32_t f2tf32(float x) {
    uint32_t r; asm("cvt.rna.tf32.f32 %0, %1;" : "=r"(r) : "f"(x)); return r;
}
__device__ __forceinline__ void mma_tf32(
    float& d0, float& d1, float& d2, float& d3,
    uint32_t a0, uint32_t a1, uint32_t a2, uint32_t a3,
    uint32_t b0, uint32_t b1)
{
    asm volatile(
        "mma.sync.aligned.m16n8k8.row.col.f32.tf32.tf32.f32 "
        "{%0,%1,%2,%3}, {%4,%5,%6,%7}, {%8,%9}, {%0,%1,%2,%3};"
        : "+f"(d0), "+f"(d1), "+f"(d2), "+f"(d3)
        : "r"(a0), "r"(a1), "r"(a2), "r"(a3), "r"(b0), "r"(b1));
}

// ---------------------------------------------------------------------------
// Pre-pass: round x, qkv_w, out_w to tf32 (stored as float bits)
// ---------------------------------------------------------------------------
#define N4X  (MR*HID/4)
#define N4WQ (3*HID*HID/4)
#define N4WO (HID*HID/4)
__global__ __launch_bounds__(256)
void prep_kernel(const float* __restrict__ x, const float* __restrict__ wq,
                 const float* __restrict__ wo)
{
    int i = blockIdx.x * blockDim.x + threadIdx.x;
    const float4* src; uint4* dst; int j;
    if (i < N4X)            { src = (const float4*)x;  dst = (uint4*)g_xa;   j = i; }
    else if (i < N4X+N4WQ)  { src = (const float4*)wq; dst = (uint4*)g_wqkv; j = i - N4X; }
    else                    { src = (const float4*)wo; dst = (uint4*)g_wout; j = i - N4X - N4WQ; }
    float4 v = src[j];
    dst[j] = make_uint4(f2tf32(v.x), f2tf32(v.y), f2tf32(v.z), f2tf32(v.w));
}

// ---------------------------------------------------------------------------
// TF32 GEMM, BK=32, double-buffered smem + register-prefetch pipeline.
// (R8-proven, unchanged.)
// ---------------------------------------------------------------------------
#define GEMM_SMEM (2*2*128*36*4)
template<int MODE>
__global__ __launch_bounds__(256, 1)
void gemm_tc(const float* __restrict__ bias, float* __restrict__ C,
             int Kd, int Nd)
{
    extern __shared__ uint32_t smem[];
    uint32_t* As = smem;                 // [2][128][36]
    uint32_t* Bs = smem + 2*128*36;      // [2][128][36]

    const int tid = threadIdx.x;
    const int lane = tid & 31, wid = tid >> 5;
    const int g = lane >> 2, t4 = lane & 3;
    const int wm = wid & 3, wn = wid >> 2;
    const int m0 = blockIdx.y << 7, n0 = blockIdx.x << 7;
    const float* Ap = (MODE == 1) ? (const float*)g_ctx : (const float*)g_xa;
    const float* Wp = (MODE == 1) ? (const float*)g_wout : (const float*)g_wqkv;

    const int lrow = tid >> 3, lc = (tid & 7) << 2;

    float acc[2][8][4];
#pragma unroll
    for (int mt = 0; mt < 2; mt++)
#pragma unroll
        for (int nt = 0; nt < 8; nt++)
#pragma unroll
            for (int r = 0; r < 4; r++) acc[mt][nt][r] = 0.f;

    uint4 ra[4], rb[4];
#define G_LDG(k0)                                                             \
    {                                                                         \
        _Pragma("unroll")                                                     \
        for (int it = 0; it < 4; it++) {                                      \
            int row = lrow + it * 32;                                         \
            ra[it] = *(const uint4*)(Ap + (m0 + row) * Kd + (k0) + lc);       \
            rb[it] = *(const uint4*)(Wp + (n0 + row) * Kd + (k0) + lc);       \
        }                                                                     \
    }
#define G_STS(st)                                                             \
    {                                                                         \
        _Pragma("unroll")                                                     \
        for (int it = 0; it < 4; it++) {                                      \
            int row = lrow + it * 32;                                         \
            *(uint4*)&As[((st) * 128 + row) * 36 + lc] = ra[it];              \
            *(uint4*)&Bs[((st) * 128 + row) * 36 + lc] = rb[it];              \
        }                                                                     \
    }

    G_LDG(0);
    G_STS(0);
    __syncthreads();

    const int KIT = Kd >> 5;
    for (int ki = 0; ki < KIT; ki++) {
        const int cur = ki & 1;
        if (ki + 1 < KIT) G_LDG((ki + 1) << 5);   // overlaps MMAs below
        const uint32_t* Ac = As + cur * (128 * 36);
        const uint32_t* Bc = Bs + cur * (128 * 36);
#pragma unroll
        for (int ks = 0; ks < 4; ks++) {
            const int kc = ks << 3;
            uint32_t af[2][4], bf[8][2];
#pragma unroll
            for (int mt = 0; mt < 2; mt++) {
                int r = wm * 32 + mt * 16;
                af[mt][0] = Ac[(r + g    ) * 36 + kc + t4];
                af[mt][1] = Ac[(r + g + 8) * 36 + kc + t4];
                af[mt][2] = Ac[(r + g    ) * 36 + kc + t4 + 4];
                af[mt][3] = Ac[(r + g + 8) * 36 + kc + t4 + 4];
            }
#pragma unroll
            for (int nt = 0; nt < 8; nt++) {
                int c = wn * 64 + nt * 8 + g;
                bf[nt][0] = Bc[c * 36 + kc + t4];
                bf[nt][1] = Bc[c * 36 + kc + t4 + 4];
            }
#pragma unroll
            for (int mt = 0; mt < 2; mt++)
#pragma unroll
                for (int nt = 0; nt < 8; nt++)
                    mma_tf32(acc[mt][nt][0], acc[mt][nt][1],
                             acc[mt][nt][2], acc[mt][nt][3],
                             af[mt][0], af[mt][1], af[mt][2], af[mt][3],
                             bf[nt][0], bf[nt][1]);
        }
        if (ki + 1 < KIT) {
            G_STS(cur ^ 1);
            __syncthreads();
        }
    }
#undef G_LDG
#undef G_STS

    // Epilogue
#pragma unroll
    for (int mt = 0; mt < 2; mt++) {
        int mA = m0 + wm * 32 + mt * 16 + g;
        int mB = mA + 8;
#pragma unroll
        for (int nt = 0; nt < 8; nt++) {
            int n = n0 + wn * 64 + nt * 8 + 2 * t4;
            float b0 = bias[n], b1 = bias[n + 1];
            float v00 = acc[mt][nt][0] + b0, v01 = acc[mt][nt][1] + b1;
            float v10 = acc[mt][nt][2] + b0, v11 = acc[mt][nt][3] + b1;
            if (MODE == 0) {
                int which = n >> 10;
                int wi = n & 1023;
                int h = wi >> 6, dd = wi & 63;
                {
                    int bb = mA >> 11, s = mA & 2047;
                    float* p = g_qkv + which * QKVSZ +
                               (((bb * NHEAD + h) * SEQ + s) << 6) + dd;
                    p[0] = __uint_as_float(f2tf32(v00));
                    p[1] = __uint_as_float(f2tf32(v01));
                }
                {
                    int bb = mB >> 11, s = mB & 2047;
                    float* p = g_qkv + which * QKVSZ +
                               (((bb * NHEAD + h) * SEQ + s) << 6) + dd;
                    p[0] = __uint_as_float(f2tf32(v10));
                    p[1] = __uint_as_float(f2tf32(v11));
                }
            } else {
                *(float2*)(C + mA * Nd + n) = make_float2(v00, v01);
                *(float2*)(C + mB * Nd + n) = make_float2(v10, v11);
            }
        }
    }
}

// ---------------------------------------------------------------------------
// TF32 flash attention, BKV=64, synchronous staging (R8-proven structure).
// ONLY change vs R8: __launch_bounds__(256, 2) caps regs at 128 so two CTAs
// fit per SM (16 warps) instead of one -- restores latency hiding.
// ---------------------------------------------------------------------------
#define ATTN_KS_OFF 0
#define ATTN_VS_OFF (64*68)
#define ATTN_PS_OFF (ATTN_VS_OFF + 64*72)
#define ATTN_MK_OFF (ATTN_PS_OFF + 8*16*68)
#define ATTN_SMEM   ((ATTN_MK_OFF + SEQ) * 4)
__global__ __launch_bounds__(256, 2)
void attn_tc(const int* __restrict__ mask)
{
    extern __shared__ uint32_t smem[];
    uint32_t* Ks = smem + ATTN_KS_OFF;   // [64][68]
    uint32_t* Vs = smem + ATTN_VS_OFF;   // [64][72]
    uint32_t* Ps = smem + ATTN_PS_OFF;   // [8][16*68]
    int*      msk = (int*)(smem + ATTN_MK_OFF);

    const int tid = threadIdx.x;
    const int lane = tid & 31, wid = tid >> 5;
    const int g = lane >> 2, t4 = lane & 3;
    const int bh = blockIdx.y;
    const int bb = bh >> 4, h = bh & 15;
    const int q0 = blockIdx.x << 7, qr = q0 + wid * 16;

    const float* Qg = g_qkv + bh * (SEQ * HD);
    const float* Kg = Qg + QKVSZ;
    const float* Vg = Qg + 2 * QKVSZ;
    uint32_t* Pw = Ps + wid * (16 * 68);

    // mask row -> smem (first read is after the first staging barrier)
#pragma unroll
    for (int it = 0; it < SEQ / 256; it++)
        msk[tid + it * 256] = mask[bb * SEQ + tid + it * 256];

    // Q fragments (16x64) with softmax scale folded in (exact: *2^-3)
    uint32_t qf[8][4];
#pragma unroll
    for (int kt = 0; kt < 8; kt++) {
        const float* qp = Qg + (qr + g) * HD + kt * 8 + t4;
        qf[kt][0] = __float_as_uint(qp[0]          * 0.125f);
        qf[kt][1] = __float_as_uint(qp[8 * HD]     * 0.125f);
        qf[kt][2] = __float_as_uint(qp[4]          * 0.125f);
        qf[kt][3] = __float_as_uint(qp[8 * HD + 4] * 0.125f);
    }

    float of[8][4];
#pragma unroll
    for (int nt = 0; nt < 8; nt++)
#pragma unroll
        for (int r = 0; r < 4; r++) of[nt][r] = 0.f;
    float m0r = -1e30f, m1r = -1e30f, l0r = 0.f, l1r = 0.f;

    for (int it = 0; it < SEQ / 64; it++) {
        const int kvb = it * 64;
        __syncthreads();   // prior-iteration reads of Ks/Vs complete
#pragma unroll
        for (int it2 = 0; it2 < 4; it2++) {
            int idx = tid + (it2 << 8);
            int row = idx >> 4, c = (idx & 15) << 2;
            *(uint4*)&Ks[row * 68 + c] =
                *(const uint4*)(Kg + (kvb + row) * HD + c);
            *(uint4*)&Vs[row * 72 + c] =
                *(const uint4*)(Vg + (kvb + row) * HD + c);
        }
        __syncthreads();

        // S = (Q*scale) * K^T (16x64 per warp)
        float sf[8][4];
#pragma unroll
        for (int nt = 0; nt < 8; nt++)
#pragma unroll
            for (int r = 0; r < 4; r++) sf[nt][r] = 0.f;
#pragma unroll
        for (int nt = 0; nt < 8; nt++)
#pragma unroll
            for (int kt = 0; kt < 8; kt++) {
                uint32_t b0 = Ks[(nt * 8 + g) * 68 + kt * 8 + t4];
                uint32_t b1 = Ks[(nt * 8 + g) * 68 + kt * 8 + t4 + 4];
                mma_tf32(sf[nt][0], sf[nt][1], sf[nt][2], sf[nt][3],
                         qf[kt][0], qf[kt][1], qf[kt][2], qf[kt][3], b0, b1);
            }

        // mask + online softmax (rows g, g+8)
        float lm0 = -1e30f, lm1 = -1e30f;
#pragma unroll
        for (int nt = 0; nt < 8; nt++) {
            int c = kvb + nt * 8 + 2 * t4;
            int k0m = msk[c], k1m = msk[c + 1];
            sf[nt][0] = k0m ? sf[nt][0] : -1e9f;
            sf[nt][1] = k1m ? sf[nt][1] : -1e9f;
            sf[nt][2] = k0m ? sf[nt][2] : -1e9f;
            sf[nt][3] = k1m ? sf[nt][3] : -1e9f;
            lm0 = fmaxf(lm0, fmaxf(sf[nt][0], sf[nt][1]));
            lm1 = fmaxf(lm1, fmaxf(sf[nt][2], sf[nt][3]));
        }
        lm0 = fmaxf(lm0, __shfl_xor_sync(0xffffffffu, lm0, 1));
        lm0 = fmaxf(lm0, __shfl_xor_sync(0xffffffffu, lm0, 2));
        lm1 = fmaxf(lm1, __shfl_xor_sync(0xffffffffu, lm1, 1));
        lm1 = fmaxf(lm1, __shfl_xor_sync(0xffffffffu, lm1, 2));
        float nm0 = fmaxf(m0r, lm0), nm1 = fmaxf(m1r, lm1);
        float cr0 = __expf(m0r - nm0), cr1 = __expf(m1r - nm1);
        m0r = nm0; m1r = nm1;

        __syncwarp();   // prior PV reads of Pw retire before overwrite
        float ls0 = 0.f, ls1 = 0.f;
#pragma unroll
        for (int nt = 0; nt < 8; nt++) {
            float p00 = __expf(sf[nt][0] - nm0);
            float p01 = __expf(sf[nt][1] - nm0);
            float p10 = __expf(sf[nt][2] - nm1);
            float p11 = __expf(sf[nt][3] - nm1);
            ls0 += p00 + p01; ls1 += p10 + p11;
            int c = nt * 8 + 2 * t4;
            Pw[g * 68 + c]           = f2tf32(p00);
            Pw[g * 68 + c + 1]       = f2tf32(p01);
            Pw[(g + 8) * 68 + c]     = f2tf32(p10);
            Pw[(g + 8) * 68 + c + 1] = f2tf32(p11);
        }
        ls0 += __shfl_xor_sync(0xffffffffu, ls0, 1);
        ls0 += __shfl_xor_sync(0xffffffffu, ls0, 2);
        ls1 += __shfl_xor_sync(0xffffffffu, ls1, 1);
        ls1 += __shfl_xor_sync(0xffffffffu, ls1, 2);
        l0r = l0r * cr0 + ls0;
        l1r = l1r * cr1 + ls1;
#pragma unroll
        for (int nt = 0; nt < 8; nt++) {
            of[nt][0] *= cr0; of[nt][1] *= cr0;
            of[nt][2] *= cr1; of[nt][3] *= cr1;
        }
        __syncwarp();

        // O += P*V  (P 16x64, V 64x64)
#pragma unroll
        for (int kt = 0; kt < 8; kt++) {
            uint32_t pa0 = Pw[g * 68 + kt * 8 + t4];
            uint32_t pa1 = Pw[(g + 8) * 68 + kt * 8 + t4];
            uint32_t pa2 = Pw[g * 68 + kt * 8 + t4 + 4];
            uint32_t pa3 = Pw[(g + 8) * 68 + kt * 8 + t4 + 4];
#pragma unroll
            for (int nt = 0; nt < 8; nt++) {
                uint32_t b0 = Vs[(kt * 8 + t4) * 72 + nt * 8 + g];
                uint32_t b1 = Vs[(kt * 8 + t4 + 4) * 72 + nt * 8 + g];
                mma_tf32(of[nt][0], of[nt][1], of[nt][2], of[nt][3],
                         pa0, pa1, pa2, pa3, b0, b1);
            }
        }
    }

    // Epilogue: normalize, round to tf32, store [b,s,h*d]
    float inv0 = 1.0f / l0r, inv1 = 1.0f / l1r;
#pragma unroll
    for (int nt = 0; nt < 8; nt++) {
        int c = h * HD + nt * 8 + 2 * t4;
        float* p0 = g_ctx + (bb * SEQ + qr + g) * HID + c;
        float* p1 = g_ctx + (bb * SEQ + qr + g + 8) * HID + c;
        *(float2*)p0 = make_float2(__uint_as_float(f2tf32(of[nt][0] * inv0)),
                                   __uint_as_float(f2tf32(of[nt][1] * inv0)));
        *(float2*)p1 = make_float2(__uint_as_float(f2tf32(of[nt][2] * inv1)),
                                   __uint_as_float(f2tf32(of[nt][3] * inv1)));
    }
}

// ---------------------------------------------------------------------------
extern "C" void kernel_launch(void* const* d_in, const int* in_sizes, int n_in,
                              void* d_out, int out_size)
{
    (void)in_sizes; (void)n_in; (void)out_size;
    const float* x     = (const float*)d_in[0];
    const int*   mask  = (const int*)  d_in[1];
    const float* qkv_w = (const float*)d_in[2];
    const float* qkv_b = (const float*)d_in[3];
    const float* out_w = (const float*)d_in[4];
    const float* out_b = (const float*)d_in[5];

    cudaFuncSetAttribute(gemm_tc<0>, cudaFuncAttributeMaxDynamicSharedMemorySize, GEMM_SMEM);
    cudaFuncSetAttribute(gemm_tc<1>, cudaFuncAttributeMaxDynamicSharedMemorySize, GEMM_SMEM);
    cudaFuncSetAttribute(attn_tc,    cudaFuncAttributeMaxDynamicSharedMemorySize, ATTN_SMEM);

    prep_kernel<<<(N4X + N4WQ + N4WO) / 256, 256>>>(x, qkv_w, out_w);
    gemm_tc<0><<<dim3(3 * HID / 128, MR / 128), 256, GEMM_SMEM>>>(qkv_b, nullptr, HID, 3 * HID);
    attn_tc<<<dim3(SEQ / 128, BH), 256, ATTN_SMEM>>>(mask);
    gemm_tc<1><<<dim3(HID / 128, MR / 128), 256, GEMM_SMEM>>>(out_b, (float*)d_out, HID, HID);
}